// round 3
// baseline (speedup 1.0000x reference)
#include <cuda_runtime.h>
#include <cstdint>

#define NV 50000
#define NE 800000
#define FIN 128
#define FH  128
#define FO  64

// ---------------- scratch (no allocs allowed) ----------------
static __device__ int   g_is64;
static __device__ int   g_src   [NE];
static __device__ int   g_dst   [NE];
static __device__ int   g_deg   [NV];
static __device__ int   g_rowptr[NV + 1];
static __device__ int   g_cursor[NV];
static __device__ int   g_col   [NE];
static __device__ float g_dinv  [NV];
static __device__ float g_hp1[(size_t)NV * FH];   // dinv-prescaled x@W1
static __device__ float g_h1 [(size_t)NV * FH];   // layer-1 activation (post relu)
static __device__ float g_hp2[(size_t)NV * FO];   // dinv-prescaled h1@W2

// ---------------- edge-index dtype probe + normalize ----------------
// If edge_index is int64 (little-endian, values < 2^31), every odd int32 word is 0.
__global__ void probe_kernel(const int* __restrict__ raw, int* __restrict__ is64) {
    int v = raw[2 * threadIdx.x + 1];
    int any = __syncthreads_or(v != 0);
    if (threadIdx.x == 0) *is64 = (any == 0) ? 1 : 0;
}

__global__ void convert_kernel(const int* __restrict__ raw, int e,
                               const int* __restrict__ is64f,
                               int* __restrict__ src, int* __restrict__ dst) {
    int i = blockIdx.x * blockDim.x + threadIdx.x;
    if (i >= e) return;
    if (*is64f) {
        src[i] = raw[2 * (size_t)i];
        dst[i] = raw[2 * ((size_t)e + i)];
    } else {
        src[i] = raw[i];
        dst[i] = raw[(size_t)e + i];
    }
}

// ---------------- degree / dinv ----------------
__global__ void zero_deg_kernel(int n, int* __restrict__ deg) {
    int i = blockIdx.x * blockDim.x + threadIdx.x;
    if (i < n) deg[i] = 0;
}

__global__ void count_deg_kernel(const int* __restrict__ dst, int e, int* __restrict__ deg) {
    int i = blockIdx.x * blockDim.x + threadIdx.x;
    if (i < e) atomicAdd(&deg[dst[i]], 1);
}

__global__ void dinv_kernel(int n, const int* __restrict__ deg, float* __restrict__ dinv) {
    int i = blockIdx.x * blockDim.x + threadIdx.x;
    if (i < n) dinv[i] = rsqrtf((float)(deg[i] + 1));        // +1 self-loop
}

// ---------------- single-block exclusive scan over deg -> rowptr, cursor ----------------
__global__ void scan_kernel(const int* __restrict__ deg, int n,
                            int* __restrict__ rowptr, int* __restrict__ cursor)
{
    __shared__ int sm[1024];
    __shared__ int carry;
    if (threadIdx.x == 0) carry = 0;
    __syncthreads();
    for (int base = 0; base < n; base += 1024) {
        int i = base + (int)threadIdx.x;
        int v = (i < n) ? deg[i] : 0;
        sm[threadIdx.x] = v;
        __syncthreads();
        for (int off = 1; off < 1024; off <<= 1) {
            int t = (threadIdx.x >= (unsigned)off) ? sm[threadIdx.x - off] : 0;
            __syncthreads();
            sm[threadIdx.x] += t;
            __syncthreads();
        }
        if (i < n) {
            int ex = carry + sm[threadIdx.x] - v;
            rowptr[i] = ex;
            cursor[i] = ex;
        }
        __syncthreads();
        if (threadIdx.x == 1023) carry += sm[1023];
        __syncthreads();
    }
    if (threadIdx.x == 0) rowptr[n] = carry;
}

// ---------------- CSR fill: col[pos] = src, grouped by dst ----------------
__global__ void fill_kernel(const int* __restrict__ src, const int* __restrict__ dst, int e,
                            int* __restrict__ cursor, int* __restrict__ col)
{
    int i = blockIdx.x * blockDim.x + threadIdx.x;
    if (i < e) {
        int pos = atomicAdd(&cursor[dst[i]], 1);
        col[pos] = src[i];
    }
}

// ---------------- GEMM: hp[row] = dinv[row] * (A[row] @ W) ----------------
template<int OUT>
__global__ __launch_bounds__(256) void gemm_kernel(
    const float* __restrict__ A, const float* __restrict__ W,
    const float* __restrict__ dinv, float* __restrict__ hp, int n)
{
    constexpr int K     = 128;
    constexpr int QUADS = OUT / 4;      // float4 column groups
    constexpr int G     = 256 / QUADS;  // row groups per block
    constexpr int U     = 4;            // rows per thread
    constexpr int TILE  = G * U;

    extern __shared__ float sm[];
    float* Ws = sm;                 // K*OUT floats
    float* Xs = sm + K * OUT;       // TILE*K floats

    const int t  = threadIdx.x;
    const int jc = t % QUADS;
    const int g  = t / QUADS;

    const float4* W4  = (const float4*)W;
    float4*       Ws4 = (float4*)Ws;
    for (int i = t; i < K * OUT / 4; i += 256) Ws4[i] = W4[i];
    __syncthreads();

    const float4* A4  = (const float4*)A;
    float4*       Xs4 = (float4*)Xs;
    float4*       hp4 = (float4*)hp;

    for (int row0 = blockIdx.x * TILE; row0 < n; row0 += gridDim.x * TILE) {
        for (int i = t; i < TILE * (K / 4); i += 256) {
            int r   = i / (K / 4);
            int c   = i % (K / 4);
            int row = row0 + r;
            Xs4[i] = (row < n) ? A4[(size_t)row * (K / 4) + c] : make_float4(0.f, 0.f, 0.f, 0.f);
        }
        __syncthreads();

        float acc[U][4];
#pragma unroll
        for (int u = 0; u < U; u++) { acc[u][0]=acc[u][1]=acc[u][2]=acc[u][3]=0.f; }

#pragma unroll 4
        for (int k = 0; k < K; k++) {
            float4 w = Ws4[k * QUADS + jc];
#pragma unroll
            for (int u = 0; u < U; u++) {
                float xv = Xs[(g * U + u) * K + k];
                acc[u][0] += xv * w.x;
                acc[u][1] += xv * w.y;
                acc[u][2] += xv * w.z;
                acc[u][3] += xv * w.w;
            }
        }

#pragma unroll
        for (int u = 0; u < U; u++) {
            int row = row0 + g * U + u;
            if (row < n) {
                float dv = dinv[row];
                hp4[(size_t)row * QUADS + jc] =
                    make_float4(acc[u][0]*dv, acc[u][1]*dv, acc[u][2]*dv, acc[u][3]*dv);
            }
        }
        __syncthreads();
    }
}

// ---------------- aggregate: out[d] = act(dinv[d]*(hp[d] + sum_src hp[src]) + b) ----------------
template<int F, bool RELU>
__global__ __launch_bounds__(256) void aggregate_kernel(
    const int* __restrict__ rowptr, const int* __restrict__ col,
    const float* __restrict__ hp, const float* __restrict__ dinv,
    const float* __restrict__ b, float* __restrict__ out, int n)
{
    constexpr int LPR = F / 4;        // lanes per node row (32 or 16)
    constexpr int SUB = 32 / LPR;     // nodes per warp (1 or 2)
    const int warp = (blockIdx.x * blockDim.x + threadIdx.x) >> 5;
    const int lane = threadIdx.x & 31;
    const int node = warp * SUB + lane / LPR;
    const int li   = lane % LPR;
    if (node >= n) return;

    const float4* hp4 = (const float4*)hp;
    float4 acc = hp4[(size_t)node * LPR + li];   // self-loop term (prescaled)

    int e0 = rowptr[node];
    int e1 = rowptr[node + 1];
    for (int e = e0; e < e1; e++) {
        int src = __ldg(&col[e]);
        float4 v = hp4[(size_t)src * LPR + li];
        acc.x += v.x; acc.y += v.y; acc.z += v.z; acc.w += v.w;
    }

    float dv = dinv[node];
    float4 bv = ((const float4*)b)[li];
    float4 o;
    o.x = fmaf(acc.x, dv, bv.x);
    o.y = fmaf(acc.y, dv, bv.y);
    o.z = fmaf(acc.z, dv, bv.z);
    o.w = fmaf(acc.w, dv, bv.w);
    if (RELU) {
        o.x = fmaxf(o.x, 0.f); o.y = fmaxf(o.y, 0.f);
        o.z = fmaxf(o.z, 0.f); o.w = fmaxf(o.w, 0.f);
    }
    ((float4*)out)[(size_t)node * LPR + li] = o;
}

// ---------------- launcher ----------------
extern "C" void kernel_launch(void* const* d_in, const int* in_sizes, int n_in,
                              void* d_out, int out_size)
{
    const float* x   = (const float*)d_in[0];
    const int*   ei  = (const int*)d_in[1];     // int32 OR int64 raw words (probed)
    const float* W1  = (const float*)d_in[2];
    const float* b1  = (const float*)d_in[3];
    const float* W2  = (const float*)d_in[4];
    const float* b2  = (const float*)d_in[5];
    float*       out = (float*)d_out;

    const int n = in_sizes[0] / FIN;   // 50000
    const int e = in_sizes[1] / 2;     // 800000 (element count, dtype-independent)

    void *p_is64, *p_src, *p_dst, *p_deg, *p_rowptr, *p_cursor, *p_col, *p_dinv, *p_hp1, *p_h1, *p_hp2;
    cudaGetSymbolAddress(&p_is64,   g_is64);
    cudaGetSymbolAddress(&p_src,    g_src);
    cudaGetSymbolAddress(&p_dst,    g_dst);
    cudaGetSymbolAddress(&p_deg,    g_deg);
    cudaGetSymbolAddress(&p_rowptr, g_rowptr);
    cudaGetSymbolAddress(&p_cursor, g_cursor);
    cudaGetSymbolAddress(&p_col,    g_col);
    cudaGetSymbolAddress(&p_dinv,   g_dinv);
    cudaGetSymbolAddress(&p_hp1,    g_hp1);
    cudaGetSymbolAddress(&p_h1,     g_h1);
    cudaGetSymbolAddress(&p_hp2,    g_hp2);
    int*   is64   = (int*)p_is64;
    int*   src    = (int*)p_src;
    int*   dst    = (int*)p_dst;
    int*   deg    = (int*)p_deg;
    int*   rowptr = (int*)p_rowptr;
    int*   cursor = (int*)p_cursor;
    int*   col    = (int*)p_col;
    float* dinv   = (float*)p_dinv;
    float* hp1    = (float*)p_hp1;
    float* h1     = (float*)p_h1;
    float* hp2    = (float*)p_hp2;

    const int smem1 = (128 * FH + 32 * 128) * (int)sizeof(float);   // 80 KB
    const int smem2 = (128 * FO + 64 * 128) * (int)sizeof(float);   // 64 KB
    cudaFuncSetAttribute((const void*)gemm_kernel<FH>, cudaFuncAttributeMaxDynamicSharedMemorySize, smem1);
    cudaFuncSetAttribute((const void*)gemm_kernel<FO>, cudaFuncAttributeMaxDynamicSharedMemorySize, smem2);

    // normalize edge index to int32 src/dst
    probe_kernel  <<<1, 256>>>(ei, is64);
    convert_kernel<<<(e + 255) / 256, 256>>>(ei, e, is64, src, dst);

    // graph structure: degrees, dinv, CSR by dst
    zero_deg_kernel <<<(n + 255) / 256, 256>>>(n, deg);
    count_deg_kernel<<<(e + 255) / 256, 256>>>(dst, e, deg);
    dinv_kernel     <<<(n + 255) / 256, 256>>>(n, deg, dinv);
    scan_kernel     <<<1, 1024>>>(deg, n, rowptr, cursor);
    fill_kernel     <<<(e + 255) / 256, 256>>>(src, dst, e, cursor, col);

    // layer 1
    gemm_kernel<FH><<<(n + 31) / 32, 256, smem1>>>(x, W1, dinv, hp1, n);
    aggregate_kernel<FH, true><<<(n * 32 + 255) / 256, 256>>>(rowptr, col, hp1, dinv, b1, h1, n);

    // layer 2
    gemm_kernel<FO><<<(n + 63) / 64, 256, smem2>>>(h1, W2, dinv, hp2, n);
    aggregate_kernel<FO, false><<<(((n + 1) / 2) * 32 + 255) / 256, 256>>>(rowptr, col, hp2, dinv, b2, out, n);
}

// round 4
// speedup vs baseline: 1.5443x; 1.5443x over previous
#include <cuda_runtime.h>
#include <cstdint>

#define NV 50000
#define NE 800000
#define FIN 128
#define FH  128
#define FO  64

// ---------------- scratch (no allocs allowed) ----------------
static __device__ int   g_is64;
static __device__ int   g_src   [NE];
static __device__ int   g_dst   [NE];
static __device__ int   g_deg   [NV];
static __device__ int   g_rowptr[NV + 1];
static __device__ int   g_cursor[NV];
static __device__ int   g_col   [NE];
static __device__ int   g_part  [256];
static __device__ float g_dinv  [NV];
static __device__ float g_hp1[(size_t)NV * FH];   // dinv-prescaled x@W1
static __device__ float g_h1 [(size_t)NV * FH];   // layer-1 activation (post relu)
static __device__ float g_hp2[(size_t)NV * FO];   // dinv-prescaled h1@W2

// ---------------- edge-index dtype probe ----------------
// If edge_index is int64 (LE, values < 2^31), every odd int32 word is 0.
__global__ void probe_kernel(const int* __restrict__ raw, int* __restrict__ is64) {
    int v = raw[2 * threadIdx.x + 1];
    int any = __syncthreads_or(v != 0);
    if (threadIdx.x == 0) *is64 = (any == 0) ? 1 : 0;
}

// normalize to int32 src/dst + count dst degrees (deg pre-zeroed)
__global__ void convert_count_kernel(const int* __restrict__ raw, int e,
                                     const int* __restrict__ is64f,
                                     int* __restrict__ src, int* __restrict__ dst,
                                     int* __restrict__ deg) {
    int i = blockIdx.x * blockDim.x + threadIdx.x;
    if (i >= e) return;
    int s, d;
    if (*is64f) {
        s = raw[2 * (size_t)i];
        d = raw[2 * ((size_t)e + i)];
    } else {
        s = raw[i];
        d = raw[(size_t)e + i];
    }
    src[i] = s;
    dst[i] = d;
    atomicAdd(&deg[d], 1);
}

// ---------------- 3-phase scan ----------------
__global__ void scan_block_kernel(const int* __restrict__ deg, int n,
                                  int* __restrict__ rowptr, int* __restrict__ part)
{
    __shared__ int sm[1024];
    int i = blockIdx.x * 1024 + threadIdx.x;
    int v = (i < n) ? deg[i] : 0;
    sm[threadIdx.x] = v;
    __syncthreads();
    for (int off = 1; off < 1024; off <<= 1) {
        int t = (threadIdx.x >= (unsigned)off) ? sm[threadIdx.x - off] : 0;
        __syncthreads();
        sm[threadIdx.x] += t;
        __syncthreads();
    }
    if (i < n) rowptr[i] = sm[threadIdx.x] - v;      // block-local exclusive
    if (threadIdx.x == 1023) part[blockIdx.x] = sm[1023];
}

__global__ void scan_part_kernel(int* __restrict__ part, int nb,
                                 int* __restrict__ rowptr, int n)
{
    __shared__ int sm[256];
    int v = (threadIdx.x < (unsigned)nb) ? part[threadIdx.x] : 0;
    sm[threadIdx.x] = v;
    __syncthreads();
    for (int off = 1; off < 256; off <<= 1) {
        int t = (threadIdx.x >= (unsigned)off) ? sm[threadIdx.x - off] : 0;
        __syncthreads();
        sm[threadIdx.x] += t;
        __syncthreads();
    }
    if (threadIdx.x < (unsigned)nb) part[threadIdx.x] = sm[threadIdx.x] - v;  // exclusive
    if (threadIdx.x == 0) rowptr[n] = sm[255];
}

__global__ void add_off_kernel(const int* __restrict__ part, int n,
                               int* __restrict__ rowptr, int* __restrict__ cursor,
                               const int* __restrict__ deg, float* __restrict__ dinv)
{
    int i = blockIdx.x * blockDim.x + threadIdx.x;
    if (i < n) {
        int r = rowptr[i] + part[i >> 10];
        rowptr[i] = r;
        cursor[i] = r;
        dinv[i]   = rsqrtf((float)(deg[i] + 1));     // +1 self-loop
    }
}

// ---------------- CSR fill: col[pos] = src, grouped by dst ----------------
__global__ void fill_kernel(const int* __restrict__ src, const int* __restrict__ dst, int e,
                            int* __restrict__ cursor, int* __restrict__ col)
{
    int i = blockIdx.x * blockDim.x + threadIdx.x;
    if (i < e) {
        int pos = atomicAdd(&cursor[dst[i]], 1);
        col[pos] = src[i];
    }
}

// ---------------- packed f32x2 fma helpers ----------------
__device__ __forceinline__ uint64_t pack2(float lo, float hi) {
    uint64_t r;
    asm("mov.b64 %0, {%1, %2};" : "=l"(r) : "f"(lo), "f"(hi));
    return r;
}
__device__ __forceinline__ void fma2(uint64_t& acc, uint64_t a, uint64_t b) {
    asm("fma.rn.f32x2 %0, %1, %2, %0;" : "+l"(acc) : "l"(a), "l"(b));
}
__device__ __forceinline__ void unpack2(uint64_t v, float& lo, float& hi) {
    asm("mov.b64 {%0, %1}, %2;" : "=f"(lo), "=f"(hi) : "l"(v));
}

// ---------------- GEMM: hp[row] = dinv[row] * (A[row] @ W) ----------------
template<int OUT>
__global__ __launch_bounds__(256) void gemm_kernel(
    const float* __restrict__ A, const float* __restrict__ W,
    const float* __restrict__ dinv, float* __restrict__ hp, int n)
{
    constexpr int K     = 128;
    constexpr int QUADS = OUT / 4;      // float4 column groups
    constexpr int G     = 256 / QUADS;  // row groups per block
    constexpr int U     = 8;            // rows per thread
    constexpr int TILE  = G * U;

    extern __shared__ float sm[];
    float* Ws = sm;                 // K*OUT floats
    float* Xs = sm + K * OUT;       // TILE*K floats

    const int t  = threadIdx.x;
    const int jc = t % QUADS;
    const int g  = t / QUADS;

    const float4* W4  = (const float4*)W;
    float4*       Ws4 = (float4*)Ws;
    for (int i = t; i < K * OUT / 4; i += 256) Ws4[i] = W4[i];
    __syncthreads();

    const float4* A4  = (const float4*)A;
    float4*       Xs4 = (float4*)Xs;
    float4*       hp4 = (float4*)hp;

    for (int row0 = blockIdx.x * TILE; row0 < n; row0 += gridDim.x * TILE) {
        for (int i = t; i < TILE * (K / 4); i += 256) {
            int r   = i / (K / 4);
            int c   = i % (K / 4);
            int row = row0 + r;
            Xs4[i] = (row < n) ? A4[(size_t)row * (K / 4) + c] : make_float4(0.f, 0.f, 0.f, 0.f);
        }
        __syncthreads();

        uint64_t alo[U], ahi[U];
#pragma unroll
        for (int u = 0; u < U; u++) { alo[u] = 0ull; ahi[u] = 0ull; }

#pragma unroll 4
        for (int k = 0; k < K; k++) {
            float4 w = Ws4[k * QUADS + jc];
            uint64_t wlo = pack2(w.x, w.y);
            uint64_t whi = pack2(w.z, w.w);
#pragma unroll
            for (int u = 0; u < U; u++) {
                float xv = Xs[(g * U + u) * K + k];
                uint64_t xx = pack2(xv, xv);
                fma2(alo[u], xx, wlo);
                fma2(ahi[u], xx, whi);
            }
        }

#pragma unroll
        for (int u = 0; u < U; u++) {
            int row = row0 + g * U + u;
            if (row < n) {
                float dv = dinv[row];
                float4 o;
                unpack2(alo[u], o.x, o.y);
                unpack2(ahi[u], o.z, o.w);
                o.x *= dv; o.y *= dv; o.z *= dv; o.w *= dv;
                hp4[(size_t)row * QUADS + jc] = o;
            }
        }
        __syncthreads();
    }
}

// ---------------- aggregate: out[d] = act(dinv[d]*(hp[d] + sum_src hp[src]) + b) ----------------
template<int F, bool RELU>
__global__ __launch_bounds__(256) void aggregate_kernel(
    const int* __restrict__ rowptr, const int* __restrict__ col,
    const float* __restrict__ hp, const float* __restrict__ dinv,
    const float* __restrict__ b, float* __restrict__ out, int n)
{
    constexpr int LPR = F / 4;        // lanes per node row (32 or 16)
    constexpr int SUB = 32 / LPR;     // nodes per warp (1 or 2)
    const int warp = (blockIdx.x * blockDim.x + threadIdx.x) >> 5;
    const int lane = threadIdx.x & 31;
    const int node = warp * SUB + lane / LPR;
    const int li   = lane % LPR;
    if (node >= n) return;

    const float4* hp4 = (const float4*)hp;
    float4 a0 = hp4[(size_t)node * LPR + li];   // self-loop term (prescaled)
    float4 a1 = make_float4(0.f, 0.f, 0.f, 0.f);
    float4 a2 = make_float4(0.f, 0.f, 0.f, 0.f);
    float4 a3 = make_float4(0.f, 0.f, 0.f, 0.f);

    int e  = rowptr[node];
    int e1 = rowptr[node + 1];

    for (; e + 4 <= e1; e += 4) {
        int s0 = __ldg(&col[e]);
        int s1 = __ldg(&col[e + 1]);
        int s2 = __ldg(&col[e + 2]);
        int s3 = __ldg(&col[e + 3]);
        float4 v0 = hp4[(size_t)s0 * LPR + li];
        float4 v1 = hp4[(size_t)s1 * LPR + li];
        float4 v2 = hp4[(size_t)s2 * LPR + li];
        float4 v3 = hp4[(size_t)s3 * LPR + li];
        a0.x += v0.x; a0.y += v0.y; a0.z += v0.z; a0.w += v0.w;
        a1.x += v1.x; a1.y += v1.y; a1.z += v1.z; a1.w += v1.w;
        a2.x += v2.x; a2.y += v2.y; a2.z += v2.z; a2.w += v2.w;
        a3.x += v3.x; a3.y += v3.y; a3.z += v3.z; a3.w += v3.w;
    }
    for (; e < e1; e++) {
        float4 v = hp4[(size_t)__ldg(&col[e]) * LPR + li];
        a0.x += v.x; a0.y += v.y; a0.z += v.z; a0.w += v.w;
    }
    a0.x += a1.x + a2.x + a3.x;
    a0.y += a1.y + a2.y + a3.y;
    a0.z += a1.z + a2.z + a3.z;
    a0.w += a1.w + a2.w + a3.w;

    float dv = dinv[node];
    float4 bv = ((const float4*)b)[li];
    float4 o;
    o.x = fmaf(a0.x, dv, bv.x);
    o.y = fmaf(a0.y, dv, bv.y);
    o.z = fmaf(a0.z, dv, bv.z);
    o.w = fmaf(a0.w, dv, bv.w);
    if (RELU) {
        o.x = fmaxf(o.x, 0.f); o.y = fmaxf(o.y, 0.f);
        o.z = fmaxf(o.z, 0.f); o.w = fmaxf(o.w, 0.f);
    }
    ((float4*)out)[(size_t)node * LPR + li] = o;
}

// ---------------- launcher ----------------
extern "C" void kernel_launch(void* const* d_in, const int* in_sizes, int n_in,
                              void* d_out, int out_size)
{
    const float* x   = (const float*)d_in[0];
    const int*   ei  = (const int*)d_in[1];     // int32 OR int64 raw words (probed)
    const float* W1  = (const float*)d_in[2];
    const float* b1  = (const float*)d_in[3];
    const float* W2  = (const float*)d_in[4];
    const float* b2  = (const float*)d_in[5];
    float*       out = (float*)d_out;

    const int n = in_sizes[0] / FIN;   // 50000
    const int e = in_sizes[1] / 2;     // 800000 (element count, dtype-independent)

    void *p_is64, *p_src, *p_dst, *p_deg, *p_rowptr, *p_cursor, *p_col, *p_part,
         *p_dinv, *p_hp1, *p_h1, *p_hp2;
    cudaGetSymbolAddress(&p_is64,   g_is64);
    cudaGetSymbolAddress(&p_src,    g_src);
    cudaGetSymbolAddress(&p_dst,    g_dst);
    cudaGetSymbolAddress(&p_deg,    g_deg);
    cudaGetSymbolAddress(&p_rowptr, g_rowptr);
    cudaGetSymbolAddress(&p_cursor, g_cursor);
    cudaGetSymbolAddress(&p_col,    g_col);
    cudaGetSymbolAddress(&p_part,   g_part);
    cudaGetSymbolAddress(&p_dinv,   g_dinv);
    cudaGetSymbolAddress(&p_hp1,    g_hp1);
    cudaGetSymbolAddress(&p_h1,     g_h1);
    cudaGetSymbolAddress(&p_hp2,    g_hp2);
    int*   is64   = (int*)p_is64;
    int*   src    = (int*)p_src;
    int*   dst    = (int*)p_dst;
    int*   deg    = (int*)p_deg;
    int*   rowptr = (int*)p_rowptr;
    int*   cursor = (int*)p_cursor;
    int*   col    = (int*)p_col;
    int*   part   = (int*)p_part;
    float* dinv   = (float*)p_dinv;
    float* hp1    = (float*)p_hp1;
    float* h1     = (float*)p_h1;
    float* hp2    = (float*)p_hp2;

    const int smem1 = (128 * FH + 64  * 128) * (int)sizeof(float);   // 96 KB
    const int smem2 = (128 * FO + 128 * 128) * (int)sizeof(float);   // 96 KB
    cudaFuncSetAttribute((const void*)gemm_kernel<FH>, cudaFuncAttributeMaxDynamicSharedMemorySize, smem1);
    cudaFuncSetAttribute((const void*)gemm_kernel<FO>, cudaFuncAttributeMaxDynamicSharedMemorySize, smem2);

    const int nb = (n + 1023) / 1024;   // 49 blocks for the scan

    // normalize edge index + degrees
    cudaMemsetAsync(deg, 0, n * sizeof(int));
    probe_kernel        <<<1, 256>>>(ei, is64);
    convert_count_kernel<<<(e + 255) / 256, 256>>>(ei, e, is64, src, dst, deg);

    // CSR by dst
    scan_block_kernel<<<nb, 1024>>>(deg, n, rowptr, part);
    scan_part_kernel <<<1, 256>>>(part, nb, rowptr, n);
    add_off_kernel   <<<(n + 255) / 256, 256>>>(part, n, rowptr, cursor, deg, dinv);
    fill_kernel      <<<(e + 255) / 256, 256>>>(src, dst, e, cursor, col);

    // layer 1  (gemm<128>: TILE=64)
    gemm_kernel<FH><<<(n + 63) / 64, 256, smem1>>>(x, W1, dinv, hp1, n);
    aggregate_kernel<FH, true><<<(n * 32 + 255) / 256, 256>>>(rowptr, col, hp1, dinv, b1, h1, n);

    // layer 2  (gemm<64>: TILE=128)
    gemm_kernel<FO><<<(n + 127) / 128, 256, smem2>>>(h1, W2, dinv, hp2, n);
    aggregate_kernel<FO, false><<<(((n + 1) / 2) * 32 + 255) / 256, 256>>>(rowptr, col, hp2, dinv, b2, out, n);
}

// round 5
// speedup vs baseline: 1.7347x; 1.1233x over previous
#include <cuda_runtime.h>
#include <cuda_fp16.h>
#include <cstdint>

#define NV 50000
#define NE 800000
#define FIN 128
#define FH  128
#define FO  64

// ---------------- scratch (no allocs allowed) ----------------
static __device__ int    g_is64;
static __device__ int    g_deg   [NV];
static __device__ int    g_rowptr[NV + 1];
static __device__ int    g_cursor[NV];
static __device__ int    g_col   [NE];
static __device__ int    g_part  [256];
static __device__ float  g_dinv  [NV];
static __device__ __half g_hp1[(size_t)NV * FH];   // dinv-prescaled x@W1   (fp16)
static __device__ float  g_h1 [(size_t)NV * FH];   // layer-1 activation    (fp32)
static __device__ __half g_hp2[(size_t)NV * FO];   // dinv-prescaled h1@W2  (fp16)

// ---------------- edge-index dtype probe ----------------
// If edge_index is int64 (LE, values < 2^31), every odd int32 word is 0.
__global__ void probe_kernel(const int* __restrict__ raw, int* __restrict__ is64) {
    int v = raw[2 * threadIdx.x + 1];
    int any = __syncthreads_or(v != 0);
    if (threadIdx.x == 0) *is64 = (any == 0) ? 1 : 0;
}

// count dst degrees straight from raw edge buffer (deg pre-zeroed)
__global__ void count_deg_kernel(const int* __restrict__ raw, int e,
                                 const int* __restrict__ is64f,
                                 int* __restrict__ deg) {
    int i = blockIdx.x * blockDim.x + threadIdx.x;
    if (i >= e) return;
    int d = (*is64f) ? raw[2 * ((size_t)e + i)] : raw[(size_t)e + i];
    atomicAdd(&deg[d], 1);
}

// ---------------- 3-phase scan ----------------
__global__ void scan_block_kernel(const int* __restrict__ deg, int n,
                                  int* __restrict__ rowptr, int* __restrict__ part)
{
    __shared__ int sm[1024];
    int i = blockIdx.x * 1024 + threadIdx.x;
    int v = (i < n) ? deg[i] : 0;
    sm[threadIdx.x] = v;
    __syncthreads();
    for (int off = 1; off < 1024; off <<= 1) {
        int t = (threadIdx.x >= (unsigned)off) ? sm[threadIdx.x - off] : 0;
        __syncthreads();
        sm[threadIdx.x] += t;
        __syncthreads();
    }
    if (i < n) rowptr[i] = sm[threadIdx.x] - v;      // block-local exclusive
    if (threadIdx.x == 1023) part[blockIdx.x] = sm[1023];
}

__global__ void scan_part_kernel(int* __restrict__ part, int nb,
                                 int* __restrict__ rowptr, int n)
{
    __shared__ int sm[256];
    int v = (threadIdx.x < (unsigned)nb) ? part[threadIdx.x] : 0;
    sm[threadIdx.x] = v;
    __syncthreads();
    for (int off = 1; off < 256; off <<= 1) {
        int t = (threadIdx.x >= (unsigned)off) ? sm[threadIdx.x - off] : 0;
        __syncthreads();
        sm[threadIdx.x] += t;
        __syncthreads();
    }
    if (threadIdx.x < (unsigned)nb) part[threadIdx.x] = sm[threadIdx.x] - v;  // exclusive
    if (threadIdx.x == 0) rowptr[n] = sm[255];
}

__global__ void add_off_kernel(const int* __restrict__ part, int n,
                               int* __restrict__ rowptr, int* __restrict__ cursor,
                               const int* __restrict__ deg, float* __restrict__ dinv)
{
    int i = blockIdx.x * blockDim.x + threadIdx.x;
    if (i < n) {
        int r = rowptr[i] + part[i >> 10];
        rowptr[i] = r;
        cursor[i] = r;
        dinv[i]   = rsqrtf((float)(deg[i] + 1));     // +1 self-loop
    }
}

// ---------------- CSR fill: col[pos] = src, grouped by dst ----------------
__global__ void fill_kernel(const int* __restrict__ raw, int e,
                            const int* __restrict__ is64f,
                            int* __restrict__ cursor, int* __restrict__ col)
{
    int i = blockIdx.x * blockDim.x + threadIdx.x;
    if (i >= e) return;
    int s, d;
    if (*is64f) {
        s = raw[2 * (size_t)i];
        d = raw[2 * ((size_t)e + i)];
    } else {
        s = raw[i];
        d = raw[(size_t)e + i];
    }
    int pos = atomicAdd(&cursor[d], 1);
    col[pos] = s;
}

// ---------------- packed f32x2 fma helpers ----------------
__device__ __forceinline__ uint64_t pack2(float lo, float hi) {
    uint64_t r;
    asm("mov.b64 %0, {%1, %2};" : "=l"(r) : "f"(lo), "f"(hi));
    return r;
}
__device__ __forceinline__ void fma2(uint64_t& acc, uint64_t a, uint64_t b) {
    asm("fma.rn.f32x2 %0, %1, %2, %0;" : "+l"(acc) : "l"(a), "l"(b));
}
__device__ __forceinline__ void unpack2(uint64_t v, float& lo, float& hi) {
    asm("mov.b64 {%0, %1}, %2;" : "=f"(lo), "=f"(hi) : "l"(v));
}

// ---------------- GEMM: hp[row] = fp16( dinv[row] * (A[row] @ W) ) ----------------
template<int OUT>
__global__ __launch_bounds__(256) void gemm_kernel(
    const float* __restrict__ A, const float* __restrict__ W,
    const float* __restrict__ dinv, __half* __restrict__ hp, int n)
{
    constexpr int K     = 128;
    constexpr int QUADS = OUT / 4;      // 4-col groups
    constexpr int G     = 256 / QUADS;  // row groups per block
    constexpr int U     = 8;            // rows per thread
    constexpr int TILE  = G * U;

    extern __shared__ float sm[];
    float* Ws = sm;                 // K*OUT floats
    float* Xs = sm + K * OUT;       // TILE*K floats

    const int t  = threadIdx.x;
    const int jc = t % QUADS;
    const int g  = t / QUADS;

    const float4* W4  = (const float4*)W;
    float4*       Ws4 = (float4*)Ws;
    for (int i = t; i < K * OUT / 4; i += 256) Ws4[i] = W4[i];
    __syncthreads();

    const float4* A4  = (const float4*)A;
    float4*       Xs4 = (float4*)Xs;
    uint2*        hp2 = (uint2*)hp;

    for (int row0 = blockIdx.x * TILE; row0 < n; row0 += gridDim.x * TILE) {
        for (int i = t; i < TILE * (K / 4); i += 256) {
            int r   = i / (K / 4);
            int c   = i % (K / 4);
            int row = row0 + r;
            Xs4[i] = (row < n) ? A4[(size_t)row * (K / 4) + c] : make_float4(0.f, 0.f, 0.f, 0.f);
        }
        __syncthreads();

        uint64_t alo[U], ahi[U];
#pragma unroll
        for (int u = 0; u < U; u++) { alo[u] = 0ull; ahi[u] = 0ull; }

#pragma unroll 4
        for (int k = 0; k < K; k++) {
            float4 w = Ws4[k * QUADS + jc];
            uint64_t wlo = pack2(w.x, w.y);
            uint64_t whi = pack2(w.z, w.w);
#pragma unroll
            for (int u = 0; u < U; u++) {
                float xv = Xs[(g * U + u) * K + k];
                uint64_t xx = pack2(xv, xv);
                fma2(alo[u], xx, wlo);
                fma2(ahi[u], xx, whi);
            }
        }

#pragma unroll
        for (int u = 0; u < U; u++) {
            int row = row0 + g * U + u;
            if (row < n) {
                float dv = dinv[row];
                float4 o;
                unpack2(alo[u], o.x, o.y);
                unpack2(ahi[u], o.z, o.w);
                __half2 plo = __floats2half2_rn(o.x * dv, o.y * dv);
                __half2 phi = __floats2half2_rn(o.z * dv, o.w * dv);
                uint2 pk;
                pk.x = *(const uint32_t*)&plo;
                pk.y = *(const uint32_t*)&phi;
                hp2[(size_t)row * QUADS + jc] = pk;
            }
        }
        __syncthreads();
    }
}

// ---------------- aggregate: out[d] = act(dinv[d]*(hp[d] + sum_src hp[src]) + b) ----------------
// hp is fp16; each lane owns 8 features (uint4 = 8 halves); fp32 accumulation.
__device__ __forceinline__ void acc8(float* a, uint4 v) {
    const __half2* ph = (const __half2*)&v;
#pragma unroll
    for (int j = 0; j < 4; j++) {
        float2 f = __half22float2(ph[j]);
        a[2 * j]     += f.x;
        a[2 * j + 1] += f.y;
    }
}

template<int F, bool RELU>
__global__ __launch_bounds__(256) void aggregate_kernel(
    const int* __restrict__ rowptr, const int* __restrict__ col,
    const __half* __restrict__ hp, const float* __restrict__ dinv,
    const float* __restrict__ b, float* __restrict__ out, int n)
{
    constexpr int LPR = F / 8;        // lanes per node row (16 or 8)
    constexpr int SUB = 32 / LPR;     // nodes per warp (2 or 4)
    const int warp = (blockIdx.x * blockDim.x + threadIdx.x) >> 5;
    const int lane = threadIdx.x & 31;
    const int node = warp * SUB + lane / LPR;
    const int li   = lane % LPR;
    if (node >= n) return;

    const uint4* hp4 = (const uint4*)hp;

    float a0[8] = {0,0,0,0,0,0,0,0};
    float a1[8] = {0,0,0,0,0,0,0,0};

    acc8(a0, hp4[(size_t)node * LPR + li]);   // self-loop term (prescaled)

    int e  = rowptr[node];
    int e1 = rowptr[node + 1];

    for (; e + 4 <= e1; e += 4) {
        int s0 = __ldg(&col[e]);
        int s1 = __ldg(&col[e + 1]);
        int s2 = __ldg(&col[e + 2]);
        int s3 = __ldg(&col[e + 3]);
        uint4 v0 = hp4[(size_t)s0 * LPR + li];
        uint4 v1 = hp4[(size_t)s1 * LPR + li];
        uint4 v2 = hp4[(size_t)s2 * LPR + li];
        uint4 v3 = hp4[(size_t)s3 * LPR + li];
        acc8(a0, v0); acc8(a1, v1); acc8(a0, v2); acc8(a1, v3);
    }
    for (; e < e1; e++) {
        acc8(a0, hp4[(size_t)__ldg(&col[e]) * LPR + li]);
    }
#pragma unroll
    for (int j = 0; j < 8; j++) a0[j] += a1[j];

    float dv = dinv[node];
    const float4* b4 = (const float4*)b;
    float4 bv0 = b4[li * 2];
    float4 bv1 = b4[li * 2 + 1];
    float4 o0, o1;
    o0.x = fmaf(a0[0], dv, bv0.x);
    o0.y = fmaf(a0[1], dv, bv0.y);
    o0.z = fmaf(a0[2], dv, bv0.z);
    o0.w = fmaf(a0[3], dv, bv0.w);
    o1.x = fmaf(a0[4], dv, bv1.x);
    o1.y = fmaf(a0[5], dv, bv1.y);
    o1.z = fmaf(a0[6], dv, bv1.z);
    o1.w = fmaf(a0[7], dv, bv1.w);
    if (RELU) {
        o0.x = fmaxf(o0.x, 0.f); o0.y = fmaxf(o0.y, 0.f);
        o0.z = fmaxf(o0.z, 0.f); o0.w = fmaxf(o0.w, 0.f);
        o1.x = fmaxf(o1.x, 0.f); o1.y = fmaxf(o1.y, 0.f);
        o1.z = fmaxf(o1.z, 0.f); o1.w = fmaxf(o1.w, 0.f);
    }
    float4* out4 = (float4*)out;
    out4[(size_t)node * (F / 4) + li * 2]     = o0;
    out4[(size_t)node * (F / 4) + li * 2 + 1] = o1;
}

// ---------------- launcher ----------------
extern "C" void kernel_launch(void* const* d_in, const int* in_sizes, int n_in,
                              void* d_out, int out_size)
{
    const float* x   = (const float*)d_in[0];
    const int*   ei  = (const int*)d_in[1];     // int32 OR int64 raw words (probed)
    const float* W1  = (const float*)d_in[2];
    const float* b1  = (const float*)d_in[3];
    const float* W2  = (const float*)d_in[4];
    const float* b2  = (const float*)d_in[5];
    float*       out = (float*)d_out;

    const int n = in_sizes[0] / FIN;   // 50000
    const int e = in_sizes[1] / 2;     // 800000 (element count, dtype-independent)

    void *p_is64, *p_deg, *p_rowptr, *p_cursor, *p_col, *p_part,
         *p_dinv, *p_hp1, *p_h1, *p_hp2;
    cudaGetSymbolAddress(&p_is64,   g_is64);
    cudaGetSymbolAddress(&p_deg,    g_deg);
    cudaGetSymbolAddress(&p_rowptr, g_rowptr);
    cudaGetSymbolAddress(&p_cursor, g_cursor);
    cudaGetSymbolAddress(&p_col,    g_col);
    cudaGetSymbolAddress(&p_part,   g_part);
    cudaGetSymbolAddress(&p_dinv,   g_dinv);
    cudaGetSymbolAddress(&p_hp1,    g_hp1);
    cudaGetSymbolAddress(&p_h1,     g_h1);
    cudaGetSymbolAddress(&p_hp2,    g_hp2);
    int*    is64   = (int*)p_is64;
    int*    deg    = (int*)p_deg;
    int*    rowptr = (int*)p_rowptr;
    int*    cursor = (int*)p_cursor;
    int*    col    = (int*)p_col;
    int*    part   = (int*)p_part;
    float*  dinv   = (float*)p_dinv;
    __half* hp1    = (__half*)p_hp1;
    float*  h1     = (float*)p_h1;
    __half* hp2    = (__half*)p_hp2;

    const int smem1 = (128 * FH + 64  * 128) * (int)sizeof(float);   // 96 KB
    const int smem2 = (128 * FO + 128 * 128) * (int)sizeof(float);   // 96 KB
    cudaFuncSetAttribute((const void*)gemm_kernel<FH>, cudaFuncAttributeMaxDynamicSharedMemorySize, smem1);
    cudaFuncSetAttribute((const void*)gemm_kernel<FO>, cudaFuncAttributeMaxDynamicSharedMemorySize, smem2);

    const int nb = (n + 1023) / 1024;   // 49 blocks for the scan

    // normalize edge index + degrees
    cudaMemsetAsync(deg, 0, n * sizeof(int));
    probe_kernel     <<<1, 256>>>(ei, is64);
    count_deg_kernel <<<(e + 255) / 256, 256>>>(ei, e, is64, deg);

    // CSR by dst
    scan_block_kernel<<<nb, 1024>>>(deg, n, rowptr, part);
    scan_part_kernel <<<1, 256>>>(part, nb, rowptr, n);
    add_off_kernel   <<<(n + 255) / 256, 256>>>(part, n, rowptr, cursor, deg, dinv);
    fill_kernel      <<<(e + 255) / 256, 256>>>(ei, e, is64, cursor, col);

    // layer 1  (gemm<128>: TILE=64; agg<128>: 2 nodes/warp)
    gemm_kernel<FH><<<(n + 63) / 64, 256, smem1>>>(x, W1, dinv, hp1, n);
    {
        int warps = (n + 1) / 2;
        aggregate_kernel<FH, true><<<(warps * 32 + 255) / 256, 256>>>(rowptr, col, hp1, dinv, b1, h1, n);
    }

    // layer 2  (gemm<64>: TILE=128; agg<64>: 4 nodes/warp)
    gemm_kernel<FO><<<(n + 127) / 128, 256, smem2>>>(h1, W2, dinv, hp2, n);
    {
        int warps = (n + 3) / 4;
        aggregate_kernel<FO, false><<<(warps * 32 + 255) / 256, 256>>>(rowptr, col, hp2, dinv, b2, out, n);
    }
}